// round 1
// baseline (speedup 1.0000x reference)
#include <cuda_runtime.h>
#include <cuda_bf16.h>
#include <math.h>

#define EPSV 1e-5f

// ---------------- scratch (static device allocation is allowed) ----------------
#define MAXN 100352
__device__ float g_scratch[(size_t)MAXN * 256];   // z, then h_tan in-place
__device__ float g_bhyp[256];
__device__ float g_consts[4];                     // c, sqrt_c, bb, maxnorm

// ---------------- prep: c = softplus(c_theta), b_hyp = exp0(bias) --------------
__global__ void prep_kernel(const float* __restrict__ bias,
                            const float* __restrict__ c_theta) {
    __shared__ float red[256];
    int t = threadIdx.x;
    float ct = c_theta[0];
    float c  = log1pf(expf(ct));
    float sc = sqrtf(c);

    float b = bias[t];
    red[t] = b * b;
    __syncthreads();
    for (int s = 128; s > 0; s >>= 1) {
        if (t < s) red[t] += red[t + s];
        __syncthreads();
    }
    float nb2 = red[0];
    __syncthreads();
    float nb = fmaxf(sqrtf(nb2), EPSV);
    float s1 = tanhf(sc * nb) / (sc * nb);
    float bh = s1 * b;
    g_bhyp[t] = bh;
    red[t] = bh * bh;
    __syncthreads();
    for (int s = 128; s > 0; s >>= 1) {
        if (t < s) red[t] += red[t + s];
        __syncthreads();
    }
    if (t == 0) {
        g_consts[0] = c;
        g_consts[1] = sc;
        g_consts[2] = red[0];                 // bb = ||b_hyp||^2
        g_consts[3] = (1.0f - EPSV) / sc;     // max norm
    }
}

// ---------------- GEMM: Z[N,256] = X[N,256] @ W[256,256] -----------------------
#define BM 64
#define BN 256
#define BK 32
__global__ __launch_bounds__(256, 2)
void gemm_kernel(const float* __restrict__ X, const float* __restrict__ W,
                 float* __restrict__ Z, int N) {
    __shared__ float As[BK][BM + 1];   // k-major, padded: conflict-free
    __shared__ float Bs[BK][BN];

    int tid = threadIdx.x;
    int tx = tid & 31;          // 0..31 -> col groups
    int ty = tid >> 5;          // 0..7  -> row groups
    int block_row = blockIdx.x * BM;

    float acc[8][8];
    #pragma unroll
    for (int i = 0; i < 8; i++)
        #pragma unroll
        for (int j = 0; j < 8; j++) acc[i][j] = 0.0f;

    for (int k0 = 0; k0 < 256; k0 += BK) {
        // load X tile (64 x 32), transposed into As[k][m]
        #pragma unroll
        for (int i = 0; i < 2; i++) {
            int r  = (tid >> 3) + i * 32;     // 0..63
            int cv = tid & 7;                 // float4 group in K
            int grow = block_row + r;
            float4 v = make_float4(0.f, 0.f, 0.f, 0.f);
            if (grow < N)
                v = *reinterpret_cast<const float4*>(X + (size_t)grow * 256 + k0 + cv * 4);
            As[cv * 4 + 0][r] = v.x;
            As[cv * 4 + 1][r] = v.y;
            As[cv * 4 + 2][r] = v.z;
            As[cv * 4 + 3][r] = v.w;
        }
        // load W tile (32 x 256)
        #pragma unroll
        for (int i = 0; i < 8; i++) {
            int rk = (tid >> 6) + i * 4;      // 0..31
            int cv = tid & 63;                // float4 col group
            float4 v = *reinterpret_cast<const float4*>(W + (size_t)(k0 + rk) * 256 + cv * 4);
            *reinterpret_cast<float4*>(&Bs[rk][cv * 4]) = v;
        }
        __syncthreads();

        #pragma unroll
        for (int k = 0; k < BK; k++) {
            float a[8], b[8];
            #pragma unroll
            for (int i = 0; i < 8; i++) a[i] = As[k][ty * 8 + i];
            float4 b0 = *reinterpret_cast<const float4*>(&Bs[k][tx * 4]);
            float4 b1 = *reinterpret_cast<const float4*>(&Bs[k][128 + tx * 4]);
            b[0]=b0.x; b[1]=b0.y; b[2]=b0.z; b[3]=b0.w;
            b[4]=b1.x; b[5]=b1.y; b[6]=b1.z; b[7]=b1.w;
            #pragma unroll
            for (int i = 0; i < 8; i++)
                #pragma unroll
                for (int j = 0; j < 8; j++)
                    acc[i][j] = fmaf(a[i], b[j], acc[i][j]);
        }
        __syncthreads();
    }

    #pragma unroll
    for (int i = 0; i < 8; i++) {
        int row = block_row + ty * 8 + i;
        if (row < N) {
            float4 o0 = make_float4(acc[i][0], acc[i][1], acc[i][2], acc[i][3]);
            float4 o1 = make_float4(acc[i][4], acc[i][5], acc[i][6], acc[i][7]);
            *reinterpret_cast<float4*>(Z + (size_t)row * 256 + tx * 4)       = o0;
            *reinterpret_cast<float4*>(Z + (size_t)row * 256 + 128 + tx * 4) = o1;
        }
    }
}

// ---------------- pointwise hyperbolic chain: z -> h_tan (in place) ------------
__device__ __forceinline__ float warp_sum(float v) {
    #pragma unroll
    for (int m = 16; m > 0; m >>= 1) v += __shfl_xor_sync(0xFFFFFFFFu, v, m);
    return v;
}
__device__ __forceinline__ float dot4(float4 a, float4 b) {
    return a.x*b.x + a.y*b.y + a.z*b.z + a.w*b.w;
}

__global__ __launch_bounds__(256)
void pointwise_kernel(float* __restrict__ z, int N) {
    int warp = (blockIdx.x * blockDim.x + threadIdx.x) >> 5;
    int lane = threadIdx.x & 31;
    if (warp >= N) return;

    float c    = g_consts[0];
    float sc   = g_consts[1];
    float bb   = g_consts[2];
    float maxn = g_consts[3];

    float4* row = reinterpret_cast<float4*>(z) + (size_t)warp * 64;
    float4 v0 = row[lane];
    float4 v1 = row[lane + 32];
    const float4* bh = reinterpret_cast<const float4*>(g_bhyp);
    float4 b0 = bh[lane];
    float4 b1 = bh[lane + 32];

    // exp_map_0(z)
    float n2 = warp_sum(dot4(v0, v0) + dot4(v1, v1));
    float nz = fmaxf(sqrtf(n2), EPSV);
    float s1 = tanhf(sc * nz) / (sc * nz);
    float aa = s1 * s1 * n2;                       // ||z_hyp||^2

    // mobius_add(z_hyp, b_hyp)
    float ab = s1 * warp_sum(dot4(v0, b0) + dot4(v1, b1));
    float t2 = 1.0f + 2.0f * c * ab;
    float ca = t2 + c * bb;                        // coef on a = z_hyp
    float cb = 1.0f - c * aa;                      // coef on b_hyp
    float den = fmaxf(t2 + c * c * aa * bb, EPSV);
    float inv = 1.0f / den;
    float ka = ca * s1 * inv;                      // applied to raw z
    float kb = cb * inv;

    float4 h0 = make_float4(ka*v0.x + kb*b0.x, ka*v0.y + kb*b0.y,
                            ka*v0.z + kb*b0.z, ka*v0.w + kb*b0.w);
    float4 h1 = make_float4(ka*v1.x + kb*b1.x, ka*v1.y + kb*b1.y,
                            ka*v1.z + kb*b1.z, ka*v1.w + kb*b1.w);

    // project + log_map_0
    float hh = warp_sum(dot4(h0, h0) + dot4(h1, h1));
    float nh = fmaxf(sqrtf(hh), EPSV);
    float scale = (nh > maxn) ? (maxn / nh) : 1.0f;
    float n3 = fmaxf(nh * scale, EPSV);
    float arg = fminf(sc * n3, 1.0f - EPSV);
    float s2 = atanhf(arg) / (sc * n3);
    float k = scale * s2;

    h0.x*=k; h0.y*=k; h0.z*=k; h0.w*=k;
    h1.x*=k; h1.y*=k; h1.z*=k; h1.w*=k;
    row[lane]      = h0;
    row[lane + 32] = h1;
}

// ---------------- edge scatter: out[row] += val * h_tan[col] -------------------
__device__ __forceinline__ void red_add_v4(float* p, float4 v) {
    asm volatile("red.global.add.v4.f32 [%0], {%1, %2, %3, %4};"
                 :: "l"(p), "f"(v.x), "f"(v.y), "f"(v.z), "f"(v.w) : "memory");
}

__global__ __launch_bounds__(256)
void scatter_kernel(const int* __restrict__ rows, const int* __restrict__ cols,
                    const float* __restrict__ vals, const float* __restrict__ htan,
                    float* __restrict__ out, int E) {
    int w    = (blockIdx.x * blockDim.x + threadIdx.x) >> 5;
    int lane = threadIdx.x & 31;
    if (w >= E) return;
    int   r = __ldg(rows + w);
    int   ci = __ldg(cols + w);
    float v = __ldg(vals + w);

    const float4* src = reinterpret_cast<const float4*>(htan + (size_t)ci * 256);
    float*        dst = out + (size_t)r * 256;

    float4 s0 = __ldg(src + lane);
    float4 s1 = __ldg(src + lane + 32);
    float4 m0 = make_float4(s0.x*v, s0.y*v, s0.z*v, s0.w*v);
    float4 m1 = make_float4(s1.x*v, s1.y*v, s1.z*v, s1.w*v);
    red_add_v4(dst + lane * 4, m0);
    red_add_v4(dst + 128 + lane * 4, m1);
}

// ---------------- relu in place ------------------------------------------------
__global__ void relu_kernel(float4* __restrict__ out, int n4) {
    int i = blockIdx.x * blockDim.x + threadIdx.x;
    int stride = gridDim.x * blockDim.x;
    for (; i < n4; i += stride) {
        float4 v = out[i];
        v.x = fmaxf(v.x, 0.f); v.y = fmaxf(v.y, 0.f);
        v.z = fmaxf(v.z, 0.f); v.w = fmaxf(v.w, 0.f);
        out[i] = v;
    }
}

// ---------------- launch -------------------------------------------------------
extern "C" void kernel_launch(void* const* d_in, const int* in_sizes, int n_in,
                              void* d_out, int out_size) {
    const float* x        = (const float*)d_in[0];
    const int*   adj_rows = (const int*)  d_in[1];
    const int*   adj_cols = (const int*)  d_in[2];
    const float* adj_vals = (const float*)d_in[3];
    const float* W        = (const float*)d_in[4];
    const float* bias     = (const float*)d_in[5];
    const float* c_theta  = (const float*)d_in[6];
    float* out = (float*)d_out;

    int N = in_sizes[0] / 256;
    int E = in_sizes[1];

    float* scratch;
    cudaGetSymbolAddress((void**)&scratch, g_scratch);

    prep_kernel<<<1, 256>>>(bias, c_theta);

    int gemm_blocks = (N + BM - 1) / BM;
    gemm_kernel<<<gemm_blocks, 256>>>(x, W, scratch, N);

    int pw_blocks = (N * 32 + 255) / 256;
    pointwise_kernel<<<pw_blocks, 256>>>(scratch, N);

    cudaMemsetAsync(d_out, 0, (size_t)out_size * sizeof(float), 0);

    int sc_blocks = (E + 7) / 8;   // 8 warps (edges) per 256-thread block
    scatter_kernel<<<sc_blocks, 256>>>(adj_rows, adj_cols, adj_vals, scratch, out, E);

    int n4 = out_size / 4;
    int relu_blocks = (n4 + 255) / 256;
    if (relu_blocks > 8192) relu_blocks = 8192;
    relu_kernel<<<relu_blocks, 256>>>((float4*)d_out, n4);
}

// round 4
// speedup vs baseline: 1.9613x; 1.9613x over previous
#include <cuda_runtime.h>
#include <cuda_bf16.h>
#include <math.h>

#define EPSV 1e-5f
#define MAXN 100352
#define MAXE 3276800

// ---------------- static device scratch ----------------
__device__ float g_scratch[(size_t)MAXN * 256];   // h_tan
__device__ float g_bhyp[256];
__device__ float g_consts[4];                     // c, sqrt_c, bb, maxnorm
__device__ int   g_count[MAXN];
__device__ int   g_rowptr[MAXN + 1];
__device__ int   g_cursor[MAXN];
__device__ int   g_bsum[256];
__device__ int2  g_edge[MAXE];                    // (col, val bits)

// ---------------- prep: c = softplus(c_theta), b_hyp = exp0(bias) --------------
__global__ void prep_kernel(const float* __restrict__ bias,
                            const float* __restrict__ c_theta) {
    __shared__ float red[256];
    int t = threadIdx.x;
    float ct = c_theta[0];
    float c  = log1pf(expf(ct));
    float sc = sqrtf(c);

    float b = bias[t];
    red[t] = b * b;
    __syncthreads();
    for (int s = 128; s > 0; s >>= 1) {
        if (t < s) red[t] += red[t + s];
        __syncthreads();
    }
    float nb2 = red[0];
    __syncthreads();
    float nb = fmaxf(sqrtf(nb2), EPSV);
    float s1 = tanhf(sc * nb) / (sc * nb);
    float bh = s1 * b;
    g_bhyp[t] = bh;
    red[t] = bh * bh;
    __syncthreads();
    for (int s = 128; s > 0; s >>= 1) {
        if (t < s) red[t] += red[t + s];
        __syncthreads();
    }
    if (t == 0) {
        g_consts[0] = c;
        g_consts[1] = sc;
        g_consts[2] = red[0];
        g_consts[3] = (1.0f - EPSV) / sc;
    }
}

// ---------------- CSR build: histogram / scan / bucket -------------------------
__global__ void hist_kernel(const int* __restrict__ rows, int* __restrict__ cnt, int E) {
    int e = blockIdx.x * blockDim.x + threadIdx.x;
    if (e < E) atomicAdd(&cnt[__ldg(rows + e)], 1);
}

#define SCAN_BLK 1024
__global__ void scan_reduce(const int* __restrict__ cnt, int* __restrict__ bsum, int N) {
    __shared__ int sh[SCAN_BLK];
    int i = blockIdx.x * SCAN_BLK + threadIdx.x;
    sh[threadIdx.x] = (i < N) ? cnt[i] : 0;
    __syncthreads();
    for (int s = SCAN_BLK / 2; s > 0; s >>= 1) {
        if (threadIdx.x < s) sh[threadIdx.x] += sh[threadIdx.x + s];
        __syncthreads();
    }
    if (threadIdx.x == 0) bsum[blockIdx.x] = sh[0];
}

__global__ void scan_bsum(int* __restrict__ bsum, int nb, int* __restrict__ rowptr, int N) {
    if (threadIdx.x == 0) {
        int acc = 0;
        for (int i = 0; i < nb; i++) { int t = bsum[i]; bsum[i] = acc; acc += t; }
        rowptr[N] = acc;
    }
}

__global__ void scan_final(const int* __restrict__ cnt, const int* __restrict__ bsum,
                           int* __restrict__ rowptr, int* __restrict__ cursor, int N) {
    __shared__ int sh[SCAN_BLK];
    int t = threadIdx.x;
    int i = blockIdx.x * SCAN_BLK + t;
    int v = (i < N) ? cnt[i] : 0;
    sh[t] = v;
    __syncthreads();
    #pragma unroll
    for (int off = 1; off < SCAN_BLK; off <<= 1) {
        int add = (t >= off) ? sh[t - off] : 0;
        __syncthreads();
        sh[t] += add;
        __syncthreads();
    }
    if (i < N) {
        int excl = sh[t] - v + bsum[blockIdx.x];
        rowptr[i] = excl;
        cursor[i] = excl;
    }
}

__global__ void bucket_kernel(const int* __restrict__ rows, const int* __restrict__ cols,
                              const float* __restrict__ vals, int* __restrict__ cursor,
                              int2* __restrict__ edge, int E) {
    int e = blockIdx.x * blockDim.x + threadIdx.x;
    if (e >= E) return;
    int r = __ldg(rows + e);
    int pos = atomicAdd(&cursor[r], 1);
    edge[pos] = make_int2(__ldg(cols + e), __float_as_int(__ldg(vals + e)));
}

// ---------------- warp reduce --------------------------------------------------
__device__ __forceinline__ float warp_sum(float v) {
    #pragma unroll
    for (int m = 16; m > 0; m >>= 1) v += __shfl_xor_sync(0xFFFFFFFFu, v, m);
    return v;
}

// ---------------- fused GEMM + hyperbolic pointwise ----------------------------
// Z[N,256] = pointwise_chain( X[N,256] @ W[256,256] )
#define BM 64
#define BK 32
__global__ __launch_bounds__(256, 2)
void gemm_fused_kernel(const float* __restrict__ X, const float* __restrict__ W,
                       float* __restrict__ Z, int N) {
    __shared__ float As[BK][BM + 1];
    __shared__ float Bs[BK][256];

    int tid = threadIdx.x;
    int tx = tid & 31;
    int ty = tid >> 5;
    int block_row = blockIdx.x * BM;

    float acc[8][8];
    #pragma unroll
    for (int i = 0; i < 8; i++)
        #pragma unroll
        for (int j = 0; j < 8; j++) acc[i][j] = 0.0f;

    for (int k0 = 0; k0 < 256; k0 += BK) {
        #pragma unroll
        for (int i = 0; i < 2; i++) {
            int r  = (tid >> 3) + i * 32;
            int cv = tid & 7;
            int grow = block_row + r;
            float4 v = make_float4(0.f, 0.f, 0.f, 0.f);
            if (grow < N)
                v = *reinterpret_cast<const float4*>(X + (size_t)grow * 256 + k0 + cv * 4);
            As[cv * 4 + 0][r] = v.x;
            As[cv * 4 + 1][r] = v.y;
            As[cv * 4 + 2][r] = v.z;
            As[cv * 4 + 3][r] = v.w;
        }
        #pragma unroll
        for (int i = 0; i < 8; i++) {
            int rk = (tid >> 6) + i * 4;
            int cv = tid & 63;
            float4 v = *reinterpret_cast<const float4*>(W + (size_t)(k0 + rk) * 256 + cv * 4);
            *reinterpret_cast<float4*>(&Bs[rk][cv * 4]) = v;
        }
        __syncthreads();

        #pragma unroll
        for (int k = 0; k < BK; k++) {
            float a[8], b[8];
            #pragma unroll
            for (int i = 0; i < 8; i++) a[i] = As[k][ty * 8 + i];
            float4 b0 = *reinterpret_cast<const float4*>(&Bs[k][tx * 4]);
            float4 b1 = *reinterpret_cast<const float4*>(&Bs[k][128 + tx * 4]);
            b[0]=b0.x; b[1]=b0.y; b[2]=b0.z; b[3]=b0.w;
            b[4]=b1.x; b[5]=b1.y; b[6]=b1.z; b[7]=b1.w;
            #pragma unroll
            for (int i = 0; i < 8; i++)
                #pragma unroll
                for (int j = 0; j < 8; j++)
                    acc[i][j] = fmaf(a[i], b[j], acc[i][j]);
        }
        __syncthreads();
    }

    // ---- fused hyperbolic epilogue: each warp owns 8 complete rows -----------
    float c    = g_consts[0];
    float scv  = g_consts[1];
    float bb   = g_consts[2];
    float maxn = g_consts[3];
    const float4* bh = reinterpret_cast<const float4*>(g_bhyp);
    float4 bv0 = bh[tx];
    float4 bv1 = bh[tx + 32];
    float bl[8] = {bv0.x, bv0.y, bv0.z, bv0.w, bv1.x, bv1.y, bv1.z, bv1.w};

    #pragma unroll
    for (int i = 0; i < 8; i++) {
        float n2l = 0.f, abl = 0.f;
        #pragma unroll
        for (int j = 0; j < 8; j++) {
            n2l = fmaf(acc[i][j], acc[i][j], n2l);
            abl = fmaf(acc[i][j], bl[j], abl);
        }
        float n2 = warp_sum(n2l);
        float ab = warp_sum(abl);

        // exp_map_0
        float nz = fmaxf(sqrtf(n2), EPSV);
        float s1 = tanhf(scv * nz) / (scv * nz);
        float aa = s1 * s1 * n2;
        ab *= s1;
        // mobius_add
        float t2 = 1.0f + 2.0f * c * ab;
        float den = fmaxf(t2 + c * c * aa * bb, EPSV);
        float inv = 1.0f / den;
        float ka = (t2 + c * bb) * s1 * inv;
        float kb = (1.0f - c * aa) * inv;

        float h[8];
        float hhl = 0.f;
        #pragma unroll
        for (int j = 0; j < 8; j++) {
            h[j] = fmaf(ka, acc[i][j], kb * bl[j]);
            hhl = fmaf(h[j], h[j], hhl);
        }
        float hh = warp_sum(hhl);

        // project + log_map_0
        float nh = fmaxf(sqrtf(hh), EPSV);
        float scale = (nh > maxn) ? (maxn / nh) : 1.0f;
        float n3 = fmaxf(nh * scale, EPSV);
        float arg = fminf(scv * n3, 1.0f - EPSV);
        float kk = scale * atanhf(arg) / (scv * n3);

        int row = block_row + ty * 8 + i;
        if (row < N) {
            float4 o0 = make_float4(kk*h[0], kk*h[1], kk*h[2], kk*h[3]);
            float4 o1 = make_float4(kk*h[4], kk*h[5], kk*h[6], kk*h[7]);
            *reinterpret_cast<float4*>(Z + (size_t)row * 256 + tx * 4)       = o0;
            *reinterpret_cast<float4*>(Z + (size_t)row * 256 + 128 + tx * 4) = o1;
        }
    }
}

// ---------------- CSR aggregation + ReLU: one warp per row ---------------------
__global__ __launch_bounds__(256)
void agg_kernel(const int* __restrict__ rowptr, const int2* __restrict__ edge,
                const float* __restrict__ htan, float* __restrict__ out, int N) {
    int r    = (blockIdx.x * blockDim.x + threadIdx.x) >> 5;
    int lane = threadIdx.x & 31;
    if (r >= N) return;

    int beg = __ldg(rowptr + r);
    int end = __ldg(rowptr + r + 1);

    float a[8] = {0.f, 0.f, 0.f, 0.f, 0.f, 0.f, 0.f, 0.f};

    int e = beg;
    for (; e + 2 <= end; e += 2) {
        int2  e0 = __ldg(edge + e);
        int2  e1 = __ldg(edge + e + 1);
        float v0 = __int_as_float(e0.y);
        float v1 = __int_as_float(e1.y);
        const float4* s0 = reinterpret_cast<const float4*>(htan + (size_t)e0.x * 256);
        const float4* s1 = reinterpret_cast<const float4*>(htan + (size_t)e1.x * 256);
        float4 x00 = __ldg(s0 + lane);
        float4 x01 = __ldg(s0 + lane + 32);
        float4 x10 = __ldg(s1 + lane);
        float4 x11 = __ldg(s1 + lane + 32);
        a[0] = fmaf(v0, x00.x, a[0]); a[1] = fmaf(v0, x00.y, a[1]);
        a[2] = fmaf(v0, x00.z, a[2]); a[3] = fmaf(v0, x00.w, a[3]);
        a[4] = fmaf(v0, x01.x, a[4]); a[5] = fmaf(v0, x01.y, a[5]);
        a[6] = fmaf(v0, x01.z, a[6]); a[7] = fmaf(v0, x01.w, a[7]);
        a[0] = fmaf(v1, x10.x, a[0]); a[1] = fmaf(v1, x10.y, a[1]);
        a[2] = fmaf(v1, x10.z, a[2]); a[3] = fmaf(v1, x10.w, a[3]);
        a[4] = fmaf(v1, x11.x, a[4]); a[5] = fmaf(v1, x11.y, a[5]);
        a[6] = fmaf(v1, x11.z, a[6]); a[7] = fmaf(v1, x11.w, a[7]);
    }
    if (e < end) {
        int2  e0 = __ldg(edge + e);
        float v0 = __int_as_float(e0.y);
        const float4* s0 = reinterpret_cast<const float4*>(htan + (size_t)e0.x * 256);
        float4 x00 = __ldg(s0 + lane);
        float4 x01 = __ldg(s0 + lane + 32);
        a[0] = fmaf(v0, x00.x, a[0]); a[1] = fmaf(v0, x00.y, a[1]);
        a[2] = fmaf(v0, x00.z, a[2]); a[3] = fmaf(v0, x00.w, a[3]);
        a[4] = fmaf(v0, x01.x, a[4]); a[5] = fmaf(v0, x01.y, a[5]);
        a[6] = fmaf(v0, x01.z, a[6]); a[7] = fmaf(v0, x01.w, a[7]);
    }

    float4 o0 = make_float4(fmaxf(a[0],0.f), fmaxf(a[1],0.f), fmaxf(a[2],0.f), fmaxf(a[3],0.f));
    float4 o1 = make_float4(fmaxf(a[4],0.f), fmaxf(a[5],0.f), fmaxf(a[6],0.f), fmaxf(a[7],0.f));
    float4* dst = reinterpret_cast<float4*>(out + (size_t)r * 256);
    dst[lane]      = o0;
    dst[lane + 32] = o1;
}

// ---------------- launch -------------------------------------------------------
extern "C" void kernel_launch(void* const* d_in, const int* in_sizes, int n_in,
                              void* d_out, int out_size) {
    const float* x        = (const float*)d_in[0];
    const int*   adj_rows = (const int*)  d_in[1];
    const int*   adj_cols = (const int*)  d_in[2];
    const float* adj_vals = (const float*)d_in[3];
    const float* W        = (const float*)d_in[4];
    const float* bias     = (const float*)d_in[5];
    const float* c_theta  = (const float*)d_in[6];
    float* out = (float*)d_out;

    int N = in_sizes[0] / 256;
    int E = in_sizes[1];

    float* scratch; cudaGetSymbolAddress((void**)&scratch, g_scratch);
    int*   cnt;     cudaGetSymbolAddress((void**)&cnt,     g_count);
    int*   rowptr;  cudaGetSymbolAddress((void**)&rowptr,  g_rowptr);
    int*   cursor;  cudaGetSymbolAddress((void**)&cursor,  g_cursor);
    int*   bsum;    cudaGetSymbolAddress((void**)&bsum,    g_bsum);
    int2*  edge;    cudaGetSymbolAddress((void**)&edge,    g_edge);

    // CSR build
    cudaMemsetAsync(cnt, 0, (size_t)N * sizeof(int), 0);
    hist_kernel<<<(E + 255) / 256, 256>>>(adj_rows, cnt, E);
    int nb = (N + SCAN_BLK - 1) / SCAN_BLK;
    scan_reduce<<<nb, SCAN_BLK>>>(cnt, bsum, N);
    scan_bsum<<<1, 32>>>(bsum, nb, rowptr, N);
    scan_final<<<nb, SCAN_BLK>>>(cnt, bsum, rowptr, cursor, N);
    bucket_kernel<<<(E + 255) / 256, 256>>>(adj_rows, adj_cols, adj_vals,
                                            cursor, edge, E);

    // fused GEMM + hyperbolic chain
    prep_kernel<<<1, 256>>>(bias, c_theta);
    int gemm_blocks = (N + BM - 1) / BM;
    gemm_fused_kernel<<<gemm_blocks, 256>>>(x, W, scratch, N);

    // CSR aggregation + ReLU
    int agg_blocks = (N * 32 + 255) / 256;
    agg_kernel<<<agg_blocks, 256>>>(rowptr, edge, scratch, out, N);
}

// round 5
// speedup vs baseline: 2.0578x; 1.0492x over previous
#include <cuda_runtime.h>
#include <cuda_bf16.h>
#include <math.h>

#define EPSV 1e-5f
#define MAXN 100352
#define MAXE 3276800

// ---------------- static device scratch ----------------
__device__ float g_scratch[(size_t)MAXN * 256];   // h_tan
__device__ float g_bhyp[256];
__device__ float g_consts[4];                     // c, sqrt_c, bb, maxnorm
__device__ int   g_count[MAXN];
__device__ int   g_rowptr[MAXN + 1];
__device__ int   g_cursor[MAXN];
__device__ int   g_bsum[256];
__device__ int2  g_edge[MAXE];                    // (col, val bits)

// ---------------- prep: c = softplus(c_theta), b_hyp = exp0(bias) --------------
__global__ void prep_kernel(const float* __restrict__ bias,
                            const float* __restrict__ c_theta) {
    __shared__ float red[256];
    int t = threadIdx.x;
    float ct = c_theta[0];
    float c  = log1pf(expf(ct));
    float sc = sqrtf(c);

    float b = bias[t];
    red[t] = b * b;
    __syncthreads();
    for (int s = 128; s > 0; s >>= 1) {
        if (t < s) red[t] += red[t + s];
        __syncthreads();
    }
    float nb2 = red[0];
    __syncthreads();
    float nb = fmaxf(sqrtf(nb2), EPSV);
    float s1 = tanhf(sc * nb) / (sc * nb);
    float bh = s1 * b;
    g_bhyp[t] = bh;
    red[t] = bh * bh;
    __syncthreads();
    for (int s = 128; s > 0; s >>= 1) {
        if (t < s) red[t] += red[t + s];
        __syncthreads();
    }
    if (t == 0) {
        g_consts[0] = c;
        g_consts[1] = sc;
        g_consts[2] = red[0];
        g_consts[3] = (1.0f - EPSV) / sc;
    }
}

// ---------------- CSR build: histogram / scan / bucket -------------------------
__global__ void hist_kernel(const int* __restrict__ rows, int* __restrict__ cnt, int E) {
    int e = blockIdx.x * blockDim.x + threadIdx.x;
    if (e < E) atomicAdd(&cnt[__ldg(rows + e)], 1);
}

#define SCAN_BLK 1024
__global__ void scan_reduce(const int* __restrict__ cnt, int* __restrict__ bsum, int N) {
    __shared__ int sh[SCAN_BLK];
    int i = blockIdx.x * SCAN_BLK + threadIdx.x;
    sh[threadIdx.x] = (i < N) ? cnt[i] : 0;
    __syncthreads();
    for (int s = SCAN_BLK / 2; s > 0; s >>= 1) {
        if (threadIdx.x < s) sh[threadIdx.x] += sh[threadIdx.x + s];
        __syncthreads();
    }
    if (threadIdx.x == 0) bsum[blockIdx.x] = sh[0];
}

__global__ void scan_bsum(int* __restrict__ bsum, int nb, int* __restrict__ rowptr, int N) {
    if (threadIdx.x == 0) {
        int acc = 0;
        for (int i = 0; i < nb; i++) { int t = bsum[i]; bsum[i] = acc; acc += t; }
        rowptr[N] = acc;
    }
}

__global__ void scan_final(const int* __restrict__ cnt, const int* __restrict__ bsum,
                           int* __restrict__ rowptr, int* __restrict__ cursor, int N) {
    __shared__ int sh[SCAN_BLK];
    int t = threadIdx.x;
    int i = blockIdx.x * SCAN_BLK + t;
    int v = (i < N) ? cnt[i] : 0;
    sh[t] = v;
    __syncthreads();
    #pragma unroll
    for (int off = 1; off < SCAN_BLK; off <<= 1) {
        int add = (t >= off) ? sh[t - off] : 0;
        __syncthreads();
        sh[t] += add;
        __syncthreads();
    }
    if (i < N) {
        int excl = sh[t] - v + bsum[blockIdx.x];
        rowptr[i] = excl;
        cursor[i] = excl;
    }
}

__global__ void bucket_kernel(const int* __restrict__ rows, const int* __restrict__ cols,
                              const float* __restrict__ vals, int* __restrict__ cursor,
                              int2* __restrict__ edge, int E) {
    int e = blockIdx.x * blockDim.x + threadIdx.x;
    if (e >= E) return;
    int r = __ldg(rows + e);
    int pos = atomicAdd(&cursor[r], 1);
    edge[pos] = make_int2(__ldg(cols + e), __float_as_int(__ldg(vals + e)));
}

// ---------------- warp reduce --------------------------------------------------
__device__ __forceinline__ float warp_sum(float v) {
    #pragma unroll
    for (int m = 16; m > 0; m >>= 1) v += __shfl_xor_sync(0xFFFFFFFFu, v, m);
    return v;
}

// ---------------- fused GEMM + hyperbolic pointwise ----------------------------
// Z[N,256] = pointwise_chain( X[N,256] @ W[256,256] )
#define BM 64
#define BK 32
__global__ __launch_bounds__(256, 2)
void gemm_fused_kernel(const float* __restrict__ X, const float* __restrict__ W,
                       float* __restrict__ Z, int N) {
    __shared__ float As[BK][BM + 1];
    __shared__ float Bs[BK][256];

    int tid = threadIdx.x;
    int tx = tid & 31;
    int ty = tid >> 5;
    int block_row = blockIdx.x * BM;

    float acc[8][8];
    #pragma unroll
    for (int i = 0; i < 8; i++)
        #pragma unroll
        for (int j = 0; j < 8; j++) acc[i][j] = 0.0f;

    for (int k0 = 0; k0 < 256; k0 += BK) {
        #pragma unroll
        for (int i = 0; i < 2; i++) {
            int r  = (tid >> 3) + i * 32;
            int cv = tid & 7;
            int grow = block_row + r;
            float4 v = make_float4(0.f, 0.f, 0.f, 0.f);
            if (grow < N)
                v = *reinterpret_cast<const float4*>(X + (size_t)grow * 256 + k0 + cv * 4);
            As[cv * 4 + 0][r] = v.x;
            As[cv * 4 + 1][r] = v.y;
            As[cv * 4 + 2][r] = v.z;
            As[cv * 4 + 3][r] = v.w;
        }
        #pragma unroll
        for (int i = 0; i < 8; i++) {
            int rk = (tid >> 6) + i * 4;
            int cv = tid & 63;
            float4 v = *reinterpret_cast<const float4*>(W + (size_t)(k0 + rk) * 256 + cv * 4);
            *reinterpret_cast<float4*>(&Bs[rk][cv * 4]) = v;
        }
        __syncthreads();

        #pragma unroll
        for (int k = 0; k < BK; k++) {
            float a[8], b[8];
            #pragma unroll
            for (int i = 0; i < 8; i++) a[i] = As[k][ty * 8 + i];
            float4 b0 = *reinterpret_cast<const float4*>(&Bs[k][tx * 4]);
            float4 b1 = *reinterpret_cast<const float4*>(&Bs[k][128 + tx * 4]);
            b[0]=b0.x; b[1]=b0.y; b[2]=b0.z; b[3]=b0.w;
            b[4]=b1.x; b[5]=b1.y; b[6]=b1.z; b[7]=b1.w;
            #pragma unroll
            for (int i = 0; i < 8; i++)
                #pragma unroll
                for (int j = 0; j < 8; j++)
                    acc[i][j] = fmaf(a[i], b[j], acc[i][j]);
        }
        __syncthreads();
    }

    // ---- fused hyperbolic epilogue: each warp owns 8 complete rows -----------
    float c    = g_consts[0];
    float scv  = g_consts[1];
    float bb   = g_consts[2];
    float maxn = g_consts[3];
    const float4* bh = reinterpret_cast<const float4*>(g_bhyp);
    float4 bv0 = bh[tx];
    float4 bv1 = bh[tx + 32];
    float bl[8] = {bv0.x, bv0.y, bv0.z, bv0.w, bv1.x, bv1.y, bv1.z, bv1.w};

    #pragma unroll
    for (int i = 0; i < 8; i++) {
        float n2l = 0.f, abl = 0.f;
        #pragma unroll
        for (int j = 0; j < 8; j++) {
            n2l = fmaf(acc[i][j], acc[i][j], n2l);
            abl = fmaf(acc[i][j], bl[j], abl);
        }
        float n2 = warp_sum(n2l);
        float ab = warp_sum(abl);

        // exp_map_0
        float nz = fmaxf(sqrtf(n2), EPSV);
        float s1 = tanhf(scv * nz) / (scv * nz);
        float aa = s1 * s1 * n2;
        ab *= s1;
        // mobius_add
        float t2 = 1.0f + 2.0f * c * ab;
        float den = fmaxf(t2 + c * c * aa * bb, EPSV);
        float inv = 1.0f / den;
        float ka = (t2 + c * bb) * s1 * inv;
        float kb = (1.0f - c * aa) * inv;

        float h[8];
        float hhl = 0.f;
        #pragma unroll
        for (int j = 0; j < 8; j++) {
            h[j] = fmaf(ka, acc[i][j], kb * bl[j]);
            hhl = fmaf(h[j], h[j], hhl);
        }
        float hh = warp_sum(hhl);

        // project + log_map_0
        float nh = fmaxf(sqrtf(hh), EPSV);
        float scale = (nh > maxn) ? (maxn / nh) : 1.0f;
        float n3 = fmaxf(nh * scale, EPSV);
        float arg = fminf(scv * n3, 1.0f - EPSV);
        float kk = scale * atanhf(arg) / (scv * n3);

        int row = block_row + ty * 8 + i;
        if (row < N) {
            float4 o0 = make_float4(kk*h[0], kk*h[1], kk*h[2], kk*h[3]);
            float4 o1 = make_float4(kk*h[4], kk*h[5], kk*h[6], kk*h[7]);
            *reinterpret_cast<float4*>(Z + (size_t)row * 256 + tx * 4)       = o0;
            *reinterpret_cast<float4*>(Z + (size_t)row * 256 + 128 + tx * 4) = o1;
        }
    }
}

// ---------------- CSR aggregation + ReLU: one warp per row ---------------------
__global__ __launch_bounds__(256)
void agg_kernel(const int* __restrict__ rowptr, const int2* __restrict__ edge,
                const float* __restrict__ htan, float* __restrict__ out, int N) {
    int r    = (blockIdx.x * blockDim.x + threadIdx.x) >> 5;
    int lane = threadIdx.x & 31;
    if (r >= N) return;

    int beg = __ldg(rowptr + r);
    int end = __ldg(rowptr + r + 1);

    float a[8] = {0.f, 0.f, 0.f, 0.f, 0.f, 0.f, 0.f, 0.f};

    int e = beg;
    for (; e + 2 <= end; e += 2) {
        int2  e0 = __ldg(edge + e);
        int2  e1 = __ldg(edge + e + 1);
        float v0 = __int_as_float(e0.y);
        float v1 = __int_as_float(e1.y);
        const float4* s0 = reinterpret_cast<const float4*>(htan + (size_t)e0.x * 256);
        const float4* s1 = reinterpret_cast<const float4*>(htan + (size_t)e1.x * 256);
        float4 x00 = __ldg(s0 + lane);
        float4 x01 = __ldg(s0 + lane + 32);
        float4 x10 = __ldg(s1 + lane);
        float4 x11 = __ldg(s1 + lane + 32);
        a[0] = fmaf(v0, x00.x, a[0]); a[1] = fmaf(v0, x00.y, a[1]);
        a[2] = fmaf(v0, x00.z, a[2]); a[3] = fmaf(v0, x00.w, a[3]);
        a[4] = fmaf(v0, x01.x, a[4]); a[5] = fmaf(v0, x01.y, a[5]);
        a[6] = fmaf(v0, x01.z, a[6]); a[7] = fmaf(v0, x01.w, a[7]);
        a[0] = fmaf(v1, x10.x, a[0]); a[1] = fmaf(v1, x10.y, a[1]);
        a[2] = fmaf(v1, x10.z, a[2]); a[3] = fmaf(v1, x10.w, a[3]);
        a[4] = fmaf(v1, x11.x, a[4]); a[5] = fmaf(v1, x11.y, a[5]);
        a[6] = fmaf(v1, x11.z, a[6]); a[7] = fmaf(v1, x11.w, a[7]);
    }
    if (e < end) {
        int2  e0 = __ldg(edge + e);
        float v0 = __int_as_float(e0.y);
        const float4* s0 = reinterpret_cast<const float4*>(htan + (size_t)e0.x * 256);
        float4 x00 = __ldg(s0 + lane);
        float4 x01 = __ldg(s0 + lane + 32);
        a[0] = fmaf(v0, x00.x, a[0]); a[1] = fmaf(v0, x00.y, a[1]);
        a[2] = fmaf(v0, x00.z, a[2]); a[3] = fmaf(v0, x00.w, a[3]);
        a[4] = fmaf(v0, x01.x, a[4]); a[5] = fmaf(v0, x01.y, a[5]);
        a[6] = fmaf(v0, x01.z, a[6]); a[7] = fmaf(v0, x01.w, a[7]);
    }

    float4 o0 = make_float4(fmaxf(a[0],0.f), fmaxf(a[1],0.f), fmaxf(a[2],0.f), fmaxf(a[3],0.f));
    float4 o1 = make_float4(fmaxf(a[4],0.f), fmaxf(a[5],0.f), fmaxf(a[6],0.f), fmaxf(a[7],0.f));
    float4* dst = reinterpret_cast<float4*>(out + (size_t)r * 256);
    dst[lane]      = o0;
    dst[lane + 32] = o1;
}

// ---------------- launch -------------------------------------------------------
extern "C" void kernel_launch(void* const* d_in, const int* in_sizes, int n_in,
                              void* d_out, int out_size) {
    const float* x        = (const float*)d_in[0];
    const int*   adj_rows = (const int*)  d_in[1];
    const int*   adj_cols = (const int*)  d_in[2];
    const float* adj_vals = (const float*)d_in[3];
    const float* W        = (const float*)d_in[4];
    const float* bias     = (const float*)d_in[5];
    const float* c_theta  = (const float*)d_in[6];
    float* out = (float*)d_out;

    int N = in_sizes[0] / 256;
    int E = in_sizes[1];

    float* scratch; cudaGetSymbolAddress((void**)&scratch, g_scratch);
    int*   cnt;     cudaGetSymbolAddress((void**)&cnt,     g_count);
    int*   rowptr;  cudaGetSymbolAddress((void**)&rowptr,  g_rowptr);
    int*   cursor;  cudaGetSymbolAddress((void**)&cursor,  g_cursor);
    int*   bsum;    cudaGetSymbolAddress((void**)&bsum,    g_bsum);
    int2*  edge;    cudaGetSymbolAddress((void**)&edge,    g_edge);

    // Side stream + fork/join events, created ONCE outside any graph capture
    // (first call is the uncaptured correctness run). Stream/event creation is
    // not device-memory allocation. Every subsequent call issues the identical
    // fork/join DAG — deterministic.
    static cudaStream_t s_csr = nullptr;
    static cudaEvent_t  ev_fork = nullptr, ev_join = nullptr;
    if (s_csr == nullptr) {
        cudaStreamCreateWithFlags(&s_csr, cudaStreamNonBlocking);
        cudaEventCreateWithFlags(&ev_fork, cudaEventDisableTiming);
        cudaEventCreateWithFlags(&ev_join, cudaEventDisableTiming);
    }

    // ---- fork: CSR build on side stream ----
    cudaEventRecord(ev_fork, 0);
    cudaStreamWaitEvent(s_csr, ev_fork, 0);

    cudaMemsetAsync(cnt, 0, (size_t)N * sizeof(int), s_csr);
    hist_kernel<<<(E + 255) / 256, 256, 0, s_csr>>>(adj_rows, cnt, E);
    int nb = (N + SCAN_BLK - 1) / SCAN_BLK;
    scan_reduce<<<nb, SCAN_BLK, 0, s_csr>>>(cnt, bsum, N);
    scan_bsum<<<1, 32, 0, s_csr>>>(bsum, nb, rowptr, N);
    scan_final<<<nb, SCAN_BLK, 0, s_csr>>>(cnt, bsum, rowptr, cursor, N);
    bucket_kernel<<<(E + 255) / 256, 256, 0, s_csr>>>(adj_rows, adj_cols, adj_vals,
                                                      cursor, edge, E);
    cudaEventRecord(ev_join, s_csr);

    // ---- main stream: prep + fused GEMM (overlaps CSR build) ----
    prep_kernel<<<1, 256>>>(bias, c_theta);
    int gemm_blocks = (N + BM - 1) / BM;
    gemm_fused_kernel<<<gemm_blocks, 256>>>(x, W, scratch, N);

    // ---- join: aggregation needs both CSR and h_tan ----
    cudaStreamWaitEvent(0, ev_join, 0);
    int agg_blocks = (N * 32 + 255) / 256;
    agg_kernel<<<agg_blocks, 256>>>(rowptr, edge, scratch, out, N);
}